// round 10
// baseline (speedup 1.0000x reference)
#include <cuda_runtime.h>
#include <cstddef>

#define FULLMASK 0xffffffffu
typedef unsigned long long u64;

// T=128, D=768, HID=768, L=3, OUT=768, LH=2304
__device__ float g_H[128 * 2304];        // h_cat per step
__device__ float g_wfT[2304 * 768];      // transposed w_final
__device__ float g_WT[768 * 2304];       // transposed W (c-major)
__device__ float g_wxb[128 * 2304];      // W@x_t + b for all t, rows global
__device__ float g_part[12 * 128 * 768]; // split-K partials

// ---------------------------------------------------------------- helpers
__device__ __forceinline__ unsigned smem_u32(const void* p) {
    unsigned a;
    asm("{ .reg .u64 t; cvta.to.shared.u64 t, %1; cvt.u32.u64 %0, t; }"
        : "=r"(a) : "l"(p));
    return a;
}
__device__ __forceinline__ void cp_async16(unsigned d, const void* src) {
    asm volatile("cp.async.ca.shared.global [%0], [%1], 16;\n" :: "r"(d), "l"(src));
}
__device__ __forceinline__ void cp_commit() { asm volatile("cp.async.commit_group;\n" ::); }
template <int N>
__device__ __forceinline__ void cp_wait() { asm volatile("cp.async.wait_group %0;\n" :: "n"(N)); }

__device__ __forceinline__ u64 fma2(u64 a, u64 b, u64 c) {
    u64 d; asm("fma.rn.f32x2 %0, %1, %2, %3;" : "=l"(d) : "l"(a), "l"(b), "l"(c)); return d;
}
__device__ __forceinline__ u64 mul2(u64 a, u64 b) {
    u64 d; asm("mul.rn.f32x2 %0, %1, %2;" : "=l"(d) : "l"(a), "l"(b)); return d;
}
__device__ __forceinline__ u64 add2(u64 a, u64 b) {
    u64 d; asm("add.rn.f32x2 %0, %1, %2;" : "=l"(d) : "l"(a), "l"(b)); return d;
}
__device__ __forceinline__ u64 pk2(float x, float y) {
    u64 d; asm("mov.b64 %0, {%1, %2};" : "=l"(d) : "f"(x), "f"(y)); return d;
}
__device__ __forceinline__ float2 up2(u64 v) {
    float2 r; asm("mov.b64 {%0, %1}, %2;" : "=f"(r.x), "=f"(r.y) : "l"(v)); return r;
}
__device__ __forceinline__ void lds2(u64& a, u64& b, unsigned addr) {
    asm volatile("ld.shared.v2.b64 {%0, %1}, [%2];" : "=l"(a), "=l"(b) : "r"(addr));
}
__device__ __forceinline__ void ldg2(u64& a, u64& b, const float* p) {
    asm volatile("ld.global.nc.v2.b64 {%0, %1}, [%2];" : "=l"(a), "=l"(b) : "l"(p));
}
__device__ __forceinline__ float sig_fast(float z) {
    float e = __expf(-z);
    return __fdividef(1.0f, 1.0f + e);
}
// packed pair reduction: 5 stages x (2 shfl.b32 + 1 add.f32x2)
__device__ __forceinline__ u64 wredsum2(u64 v) {
#pragma unroll
    for (int m = 16; m >= 1; m >>= 1) {
        unsigned lo, hi;
        asm volatile("mov.b64 {%0, %1}, %2;" : "=r"(lo), "=r"(hi) : "l"(v));
        lo = __shfl_xor_sync(FULLMASK, lo, m);
        hi = __shfl_xor_sync(FULLMASK, hi, m);
        u64 o; asm volatile("mov.b64 %0, {%1, %2};" : "=l"(o) : "r"(lo), "r"(hi));
        v = add2(v, o);
    }
    return v;
}
__device__ __forceinline__ float hsum(u64 v) { float2 f = up2(v); return f.x + f.y; }

// ---------------------------------------------------------------- kernel 0: transposes
// bid<432: wf [768][2304] -> g_wfT [2304][768] (12 x 36 tiles)
// bid>=432: W (flat [2304][768]) -> g_WT [768][2304] (36 x 12 tiles)
__global__ void __launch_bounds__(256) k_pre(const float* __restrict__ wf,
                                             const float* __restrict__ W) {
    __shared__ float tile[64 * 65];
    const int bid = blockIdx.x;
    const float* src; float* dst; int C, R, r0, c0;
    if (bid < 432) {
        src = wf; dst = g_wfT; R = 768; C = 2304;
        r0 = (bid % 12) * 64; c0 = (bid / 12) * 64;
    } else {
        int bb = bid - 432;
        src = W; dst = g_WT; R = 2304; C = 768;
        r0 = (bb % 36) * 64; c0 = (bb / 36) * 64;
    }
    const int tid = threadIdx.x;
    const int rr = tid >> 4, cc = (tid & 15) * 4;
#pragma unroll
    for (int i = 0; i < 4; i++) {
        int r = rr + 16 * i;
        float4 v = *(const float4*)(src + (size_t)(r0 + r) * C + c0 + cc);
        tile[r * 65 + cc + 0] = v.x; tile[r * 65 + cc + 1] = v.y;
        tile[r * 65 + cc + 2] = v.z; tile[r * 65 + cc + 3] = v.w;
    }
    __syncthreads();
#pragma unroll
    for (int i = 0; i < 4; i++) {
        int jj = rr + 16 * i;
        float4 v;
        v.x = tile[(cc + 0) * 65 + jj];
        v.y = tile[(cc + 1) * 65 + jj];
        v.z = tile[(cc + 2) * 65 + jj];
        v.w = tile[(cc + 3) * 65 + jj];
        *(float4*)(dst + (size_t)(c0 + jj) * R + r0 + cc) = v;
    }
}

// ---------------------------------------------------------------- kernel 1: WXB GEMM (reduction-free)
// g_wxb[t][r] = sum_c WT[c][r] * x[t][c] + b[r].  grid (9 r-tiles, 16 t-tiles of 8).
__global__ void __launch_bounds__(256) k_wxb(const float* __restrict__ x_seq,
                                             const float* __restrict__ b) {
    __shared__ __align__(16) float xs[768 * 8];   // [c][t] 24KB
    const int tid = threadIdx.x;
    const int r = blockIdx.x * 256 + tid;
    const int t0 = blockIdx.y * 8;
    // stage x [8 t][768 c] -> xs[c][8 t]
#pragma unroll
    for (int i = 0; i < 24; i++) {
        int idx = tid + 256 * i;              // 0..6143
        int t = idx / 768; int c = idx - t * 768;
        xs[c * 8 + t] = x_seq[(size_t)(t0 + t) * 768 + c];
    }
    __syncthreads();

    u64 acc[4];
#pragma unroll
    for (int i = 0; i < 4; i++) acc[i] = 0;
    const float* wp = g_WT + r;
    const unsigned hx = smem_u32(xs);
#pragma unroll 4
    for (int c = 0; c < 768; c++) {
        float wv = __ldg(wp + (size_t)c * 2304);
        u64 w2 = pk2(wv, wv);
        u64 x01, x23, x45, x67;
        lds2(x01, x23, hx + c * 32);
        lds2(x45, x67, hx + c * 32 + 16);
        acc[0] = fma2(w2, x01, acc[0]);
        acc[1] = fma2(w2, x23, acc[1]);
        acc[2] = fma2(w2, x45, acc[2]);
        acc[3] = fma2(w2, x67, acc[3]);
    }
    const float bb = __ldg(b + r);
#pragma unroll
    for (int tp = 0; tp < 4; tp++) {
        float2 v = up2(acc[tp]);
        g_wxb[(size_t)(t0 + 2 * tp) * 2304 + r]     = v.x + bb;
        g_wxb[(size_t)(t0 + 2 * tp + 1) * 2304 + r] = v.y + bb;
    }
}

// ---------------------------------------------------------------- shared memory for scan
struct ScanSmem {
    float wxb[2048];                       // [t][16 rows]
    __align__(16) float xb[2 * 4 * 768];   // x double buffer
    u64 red[2][8][2][4];                   // [batch parity][row pair][col half][A,B,C,(pad)]
};

// ---------------------------------------------------------------- kernel 2: the scan
// 144 CTAs x 512 threads. CTA: layer l=bid/48, rows [(bid%48)*16,+16).
// Warp w: row pair p=w&7 (rows 2p,2p+1), column half hf=w>>3 (cols [384hf,384hf+384)).
// Lane owns cols {384hf + 4lane + 128kk : kk<3} per row.
__global__ void __launch_bounds__(512, 1) k_scan(
    const float* __restrict__ x_seq, const float* __restrict__ W,
    const float* __restrict__ lam,
    const float* __restrict__ eta0, const float* __restrict__ eta1p,
    const float* __restrict__ eta2, const float* __restrict__ P_init)
{
    __shared__ ScanSmem sm;
    const int tid = threadIdx.x;
    const int bid = blockIdx.x;
    const int l  = bid / 48;
    const int rb = (bid % 48) * 16;
    const int w = tid >> 5, lane = tid & 31;
    const int p = w & 7, hf = w >> 3;
    const int r0 = 2 * p;
    const int gr0 = rb + r0, gr1 = gr0 + 1;
    const float* Wl = W + (size_t)l * 589824;
    const int cb = hf * 384 + 4 * lane;

    // ---- prefetch wxb slice: sm.wxb[t*16+rl] = g_wxb[t][l*768+rb+rl]
    {
        const int base = l * 768 + rb;
#pragma unroll
        for (int i = 0; i < 4; i++) {
            int idx = tid + 512 * i;          // 0..2047
            int t = idx >> 4, rl = idx & 15;
            sm.wxb[idx] = __ldg(g_wxb + (size_t)t * 2304 + base + rl);
        }
    }

    // ---- persistent state (unified A/M): A: q=P, e=eta, escal=1 | M: q=W.P, e=W, escal=eta1
    u64 q0[6], q1[6], e0[6], e1[6];
    const float* Pl = P_init + (size_t)l * 589824;
#pragma unroll
    for (int kk = 0; kk < 3; kk++) {
        ldg2(q0[2 * kk], q0[2 * kk + 1], Pl + (size_t)gr0 * 768 + cb + 128 * kk);
        ldg2(q1[2 * kk], q1[2 * kk + 1], Pl + (size_t)gr1 * 768 + cb + 128 * kk);
    }
    const float* ep = (l == 0) ? eta0 : ((l == 2) ? eta2 : Wl);
#pragma unroll
    for (int kk = 0; kk < 3; kk++) {
        ldg2(e0[2 * kk], e0[2 * kk + 1], ep + (size_t)gr0 * 768 + cb + 128 * kk);
        ldg2(e1[2 * kk], e1[2 * kk + 1], ep + (size_t)gr1 * 768 + cb + 128 * kk);
    }
    if (l == 1) {
#pragma unroll
        for (int k = 0; k < 6; k++) { q0[k] = mul2(q0[k], e0[k]); q1[k] = mul2(q1[k], e1[k]); }
    }
    const float decay = 1.0f / (1.0f + __expf(-lam[l]));
    const float escal = (l == 1) ? eta1p[0] : 1.0f;
    const float d2v = decay * decay;
    const float a0c = decay * escal;
    const u64 d2p = pk2(d2v, d2v);
    const int gc0 = l * 768 + rb + r0;
    const unsigned xbs = smem_u32(sm.xb);
    const unsigned reds = smem_u32(&sm.red[0][0][0][0]);
    const unsigned rd0 = reds + (p * 2 + 0) * 4 * 8;       // red[0][p][0]
    const unsigned rd1 = reds + (p * 2 + 1) * 4 * 8;       // red[0][p][1]
    const unsigned PAR = 8 * 2 * 4 * 8;                    // parity stride (bytes)

    // ---- preload chunk 0 (4 steps = 768 float4)
#pragma unroll
    for (int i = 0; i < 2; i++) {
        int idx = tid + 512 * i;
        if (idx < 768) cp_async16(xbs + 16 * idx, x_seq + 4 * idx);
    }
    cp_commit(); cp_wait<0>();
    __syncthreads();

    // ---- the scan: 32 chunks x (2 batches of 2 steps)
    for (int c = 0; c < 32; c++) {
        if (c < 31) {
            const float* src = x_seq + (size_t)(c + 1) * 3072;
            unsigned dst = xbs + ((c + 1) & 1) * 12288;
#pragma unroll
            for (int i = 0; i < 2; i++) {
                int idx = tid + 512 * i;
                if (idx < 768) cp_async16(dst + 16 * idx, src + 4 * idx);
            }
            cp_commit();
        }
        const unsigned xcs = xbs + (c & 1) * 12288 + hf * 1536 + 16 * lane;
#pragma unroll
        for (int half = 0; half < 2; half++) {
            const int t = c * 4 + half * 2;
            const unsigned xa = xcs + (half * 2) * 3072;
            u64 x0[6], x1[6];
#pragma unroll
            for (int kk = 0; kk < 3; kk++) {
                lds2(x0[2 * kk], x0[2 * kk + 1], xa + 512 * kk);
                lds2(x1[2 * kk], x1[2 * kk + 1], xa + 3072 + 512 * kk);
            }
            // 6 independent half-dots (h-independent)
            u64 au00 = 0, au10 = 0, au01 = 0, au11 = 0, av0 = 0, av1 = 0;
#pragma unroll
            for (int k = 0; k < 6; k++) {
                u64 wk = mul2(x0[k], x1[k]);
                au00 = fma2(q0[k], x0[k], au00);
                au10 = fma2(q0[k], x1[k], au10);
                au01 = fma2(q1[k], x0[k], au01);
                au11 = fma2(q1[k], x1[k], au11);
                av0  = fma2(e0[k], wk, av0);
                av1  = fma2(e1[k], wk, av1);
            }
            u64 A = wredsum2(pk2(hsum(au00), hsum(au10)));
            u64 B = wredsum2(pk2(hsum(au01), hsum(au11)));
            u64 C = wredsum2(pk2(hsum(av0),  hsum(av1)));
            // publish this half's partials; parity == half (2 batches per chunk)
            if (lane == 0) {
                u64* rp = (u64*)&sm.red[half][p][hf][0];
                rp[0] = A; rp[1] = B; rp[2] = C;
            }
            if (half == 1) cp_wait<0>();     // own cp slices done before the bar
            __syncthreads();                 // publishes red[] and (half==1) the x tile
            // combine both halves (broadcast reads)
            {
                const unsigned b0 = rd0 + half * PAR;
                const unsigned b1 = rd1 + half * PAR;
                u64 A0, B0, C0x, A1, B1, C1x;
                lds2(A0, B0, b0); lds2(A1, B1, b1);
                asm volatile("ld.shared.b64 %0, [%1];" : "=l"(C0x) : "r"(b0 + 16));
                asm volatile("ld.shared.b64 %0, [%1];" : "=l"(C1x) : "r"(b1 + 16));
                A = add2(A0, A1); B = add2(B0, B1); C = add2(C0x, C1x);
            }
            float2 fa = up2(A), fb = up2(B), fc = up2(C);
            const float2 wx0 = *(const float2*)(sm.wxb + t * 16 + r0);
            const float2 wx1 = *(const float2*)(sm.wxb + (t + 1) * 16 + r0);
            float h00 = sig_fast(fa.x + wx0.x);
            float h01 = sig_fast(fb.x + wx0.y);
            float h10 = sig_fast(fmaf(decay, fa.y, fmaf(escal * h00, fc.x, wx1.x)));
            float h11 = sig_fast(fmaf(decay, fb.y, fmaf(escal * h01, fc.y, wx1.y)));
            if (hf == 0 && lane == 0) {
                float2 hv0; hv0.x = h00; hv0.y = h01;
                float2 hv1; hv1.x = h10; hv1.y = h11;
                *(float2*)(g_H + (size_t)t * 2304 + gc0) = hv0;
                *(float2*)(g_H + (size_t)(t + 1) * 2304 + gc0) = hv1;
            }
            // batched update: q = d2*q + e .* (a0*x0 + a1*x1)
            const u64 p00 = pk2(a0c * h00, a0c * h00);
            const u64 p10 = pk2(escal * h10, escal * h10);
            const u64 p01 = pk2(a0c * h01, a0c * h01);
            const u64 p11 = pk2(escal * h11, escal * h11);
#pragma unroll
            for (int k = 0; k < 6; k++) {
                u64 z0 = fma2(p10, x1[k], mul2(p00, x0[k]));
                q0[k] = fma2(e0[k], z0, mul2(q0[k], d2p));
                u64 z1 = fma2(p11, x1[k], mul2(p01, x0[k]));
                q1[k] = fma2(e1[k], z1, mul2(q1[k], d2p));
            }
        }
    }
}

// ---------------------------------------------------------------- kernel 3: readout GEMM (split-K 12)
__global__ void __launch_bounds__(256) k_gemm() {
    __shared__ __align__(16) float Hs[192 * 36];  // [192 j][32 t + pad 4]
    const int ob = blockIdx.x, tb = blockIdx.y, kb = blockIdx.z;
    const int tid = threadIdx.x;
    const int t0 = tb * 32;
#pragma unroll
    for (int i = 0; i < 24; i++) {
        int idx = tid + 256 * i;
        int tl = idx / 192, jl = idx - tl * 192;
        Hs[jl * 36 + tl] = g_H[(size_t)(t0 + tl) * 2304 + kb * 192 + jl];
    }
    __syncthreads();

    u64 acc[16];
#pragma unroll
    for (int i = 0; i < 16; i++) acc[i] = 0;

    const int o = ob * 256 + tid;
    const float* wp = g_wfT + (size_t)(kb * 192) * 768 + o;
    const unsigned hs = smem_u32(Hs);
#pragma unroll 8
    for (int j = 0; j < 192; j++) {
        float wv = __ldg(wp + (size_t)j * 768);
        u64 w2 = pk2(wv, wv);
        const unsigned ha = hs + j * 144;
#pragma unroll
        for (int u = 0; u < 8; u++) {
            u64 h0, h1; lds2(h0, h1, ha + 16 * u);
            acc[2 * u]     = fma2(w2, h0, acc[2 * u]);
            acc[2 * u + 1] = fma2(w2, h1, acc[2 * u + 1]);
        }
    }
    float* pp = g_part + (size_t)kb * 98304 + (size_t)t0 * 768 + o;
#pragma unroll
    for (int u = 0; u < 8; u++) {
        float2 v0 = up2(acc[2 * u]), v1 = up2(acc[2 * u + 1]);
        pp[(size_t)(4 * u + 0) * 768] = v0.x;
        pp[(size_t)(4 * u + 1) * 768] = v0.y;
        pp[(size_t)(4 * u + 2) * 768] = v1.x;
        pp[(size_t)(4 * u + 3) * 768] = v1.y;
    }
}

// ---------------------------------------------------------------- kernel 4: reduce + bias + sigmoid
__global__ void __launch_bounds__(256) k_reduce(const float* __restrict__ bf,
                                                float* __restrict__ y) {
    const int i = blockIdx.x * 256 + threadIdx.x;  // 0..98303
    int o = i % 768;
    float v[12];
#pragma unroll
    for (int k = 0; k < 12; k++) v[k] = __ldg(g_part + (size_t)k * 98304 + i);
    float s01 = v[0] + v[1], s23 = v[2] + v[3], s45 = v[4] + v[5];
    float s67 = v[6] + v[7], s89 = v[8] + v[9], sab = v[10] + v[11];
    float s = ((s01 + s23) + (s45 + s67)) + ((s89 + sab) + __ldg(bf + o));
    y[i] = sig_fast(s);
}

// ---------------------------------------------------------------- launch
extern "C" void kernel_launch(void* const* d_in, const int* in_sizes, int n_in,
                              void* d_out, int out_size) {
    const float* x    = (const float*)d_in[0];  // (128, 768)
    const float* W    = (const float*)d_in[1];  // (3, 768, 768)
    const float* b    = (const float*)d_in[2];  // (3, 768)
    const float* lam  = (const float*)d_in[3];  // (3,)
    const float* eta0 = (const float*)d_in[4];  // (768, 768)
    const float* eta1 = (const float*)d_in[5];  // scalar
    const float* eta2 = (const float*)d_in[6];  // (768, 768)
    const float* wf   = (const float*)d_in[7];  // (768, 2304)
    const float* bf   = (const float*)d_in[8];  // (768,)
    const float* P0   = (const float*)d_in[9];  // (3, 768, 768)
    float* y = (float*)d_out;                   // (128, 768)

    k_pre<<<864, 256>>>(wf, W);
    k_wxb<<<dim3(9, 16), 256>>>(x, b);
    k_scan<<<144, 512>>>(x, W, lam, eta0, eta1, eta2, P0);
    k_gemm<<<dim3(3, 4, 12), 256>>>();
    k_reduce<<<384, 256>>>(bf, y);
}

// round 11
// speedup vs baseline: 1.0828x; 1.0828x over previous
#include <cuda_runtime.h>
#include <cstddef>

#define FULLMASK 0xffffffffu
typedef unsigned long long u64;

// T=128, D=768, HID=768, L=3, OUT=768, LH=2304
__device__ float g_H[128 * 2304];        // h_cat per step
__device__ float g_wfT[2304 * 768];      // transposed w_final
__device__ float g_WT[768 * 2304];       // transposed W (c-major)
__device__ float g_wxb[128 * 2304];      // W@x_t + b for all t
__device__ float g_part[12 * 128 * 768]; // split-K partials

// ---------------------------------------------------------------- helpers
__device__ __forceinline__ unsigned smem_u32(const void* p) {
    unsigned a;
    asm("{ .reg .u64 t; cvta.to.shared.u64 t, %1; cvt.u32.u64 %0, t; }"
        : "=r"(a) : "l"(p));
    return a;
}
__device__ __forceinline__ void cp_async16(unsigned d, const void* src) {
    asm volatile("cp.async.ca.shared.global [%0], [%1], 16;\n" :: "r"(d), "l"(src));
}
__device__ __forceinline__ void cp_commit() { asm volatile("cp.async.commit_group;\n" ::); }
template <int N>
__device__ __forceinline__ void cp_wait() { asm volatile("cp.async.wait_group %0;\n" :: "n"(N)); }

__device__ __forceinline__ u64 fma2(u64 a, u64 b, u64 c) {
    u64 d; asm("fma.rn.f32x2 %0, %1, %2, %3;" : "=l"(d) : "l"(a), "l"(b), "l"(c)); return d;
}
__device__ __forceinline__ u64 mul2(u64 a, u64 b) {
    u64 d; asm("mul.rn.f32x2 %0, %1, %2;" : "=l"(d) : "l"(a), "l"(b)); return d;
}
__device__ __forceinline__ u64 add2(u64 a, u64 b) {
    u64 d; asm("add.rn.f32x2 %0, %1, %2;" : "=l"(d) : "l"(a), "l"(b)); return d;
}
__device__ __forceinline__ u64 pk2(float x, float y) {
    u64 d; asm("mov.b64 %0, {%1, %2};" : "=l"(d) : "f"(x), "f"(y)); return d;
}
__device__ __forceinline__ float2 up2(u64 v) {
    float2 r; asm("mov.b64 {%0, %1}, %2;" : "=f"(r.x), "=f"(r.y) : "l"(v)); return r;
}
__device__ __forceinline__ void lds2(u64& a, u64& b, unsigned addr) {
    asm volatile("ld.shared.v2.b64 {%0, %1}, [%2];" : "=l"(a), "=l"(b) : "r"(addr));
}
__device__ __forceinline__ void ldg2(u64& a, u64& b, const float* p) {
    asm volatile("ld.global.nc.v2.b64 {%0, %1}, [%2];" : "=l"(a), "=l"(b) : "l"(p));
}
__device__ __forceinline__ float sig_fast(float z) {
    float e = __expf(-z);
    return __fdividef(1.0f, 1.0f + e);
}
// packed pair reduction: 5 stages x (2 shfl.b32 + 1 add.f32x2)
__device__ __forceinline__ u64 wredsum2(u64 v) {
#pragma unroll
    for (int m = 16; m >= 1; m >>= 1) {
        unsigned lo, hi;
        asm volatile("mov.b64 {%0, %1}, %2;" : "=r"(lo), "=r"(hi) : "l"(v));
        lo = __shfl_xor_sync(FULLMASK, lo, m);
        hi = __shfl_xor_sync(FULLMASK, hi, m);
        u64 o; asm volatile("mov.b64 %0, {%1, %2};" : "=l"(o) : "r"(lo), "r"(hi));
        v = add2(v, o);
    }
    return v;
}
__device__ __forceinline__ float hsum(u64 v) { float2 f = up2(v); return f.x + f.y; }

// ---------------------------------------------------------------- kernel 0: transposes
// bid<432: wf [768][2304] -> g_wfT [2304][768].  bid>=432: W [2304][768] -> g_WT [768][2304].
__global__ void __launch_bounds__(256) k_pre(const float* __restrict__ wf,
                                             const float* __restrict__ W) {
    __shared__ float tile[64 * 65];
    const int bid = blockIdx.x;
    const float* src; float* dst; int C, R, r0, c0;
    if (bid < 432) {
        src = wf; dst = g_wfT; R = 768; C = 2304;
        r0 = (bid % 12) * 64; c0 = (bid / 12) * 64;
    } else {
        int bb = bid - 432;
        src = W; dst = g_WT; R = 2304; C = 768;
        r0 = (bb % 36) * 64; c0 = (bb / 36) * 64;
    }
    const int tid = threadIdx.x;
    const int rr = tid >> 4, cc = (tid & 15) * 4;
#pragma unroll
    for (int i = 0; i < 4; i++) {
        int r = rr + 16 * i;
        float4 v = *(const float4*)(src + (size_t)(r0 + r) * C + c0 + cc);
        tile[r * 65 + cc + 0] = v.x; tile[r * 65 + cc + 1] = v.y;
        tile[r * 65 + cc + 2] = v.z; tile[r * 65 + cc + 3] = v.w;
    }
    __syncthreads();
#pragma unroll
    for (int i = 0; i < 4; i++) {
        int jj = rr + 16 * i;
        float4 v;
        v.x = tile[(cc + 0) * 65 + jj];
        v.y = tile[(cc + 1) * 65 + jj];
        v.z = tile[(cc + 2) * 65 + jj];
        v.w = tile[(cc + 3) * 65 + jj];
        *(float4*)(dst + (size_t)(c0 + jj) * R + r0 + cc) = v;
    }
}

// ---------------------------------------------------------------- kernel 1: WXB GEMM (reduction-free)
// g_wxb[t][r] = sum_c WT[c][r] * x[t][c] + b[r].  grid (9 r-tiles, 16 t-tiles of 8).
__global__ void __launch_bounds__(256) k_wxb(const float* __restrict__ x_seq,
                                             const float* __restrict__ b) {
    __shared__ __align__(16) float xs[768 * 8];   // [c][t] 24KB
    const int tid = threadIdx.x;
    const int r = blockIdx.x * 256 + tid;
    const int t0 = blockIdx.y * 8;
#pragma unroll
    for (int i = 0; i < 24; i++) {
        int idx = tid + 256 * i;
        int t = idx / 768; int c = idx - t * 768;
        xs[c * 8 + t] = x_seq[(size_t)(t0 + t) * 768 + c];
    }
    __syncthreads();

    u64 acc[4];
#pragma unroll
    for (int i = 0; i < 4; i++) acc[i] = 0;
    const float* wp = g_WT + r;
    const unsigned hx = smem_u32(xs);
#pragma unroll 4
    for (int c = 0; c < 768; c++) {
        float wv = __ldg(wp + (size_t)c * 2304);
        u64 w2 = pk2(wv, wv);
        u64 x01, x23, x45, x67;
        lds2(x01, x23, hx + c * 32);
        lds2(x45, x67, hx + c * 32 + 16);
        acc[0] = fma2(w2, x01, acc[0]);
        acc[1] = fma2(w2, x23, acc[1]);
        acc[2] = fma2(w2, x45, acc[2]);
        acc[3] = fma2(w2, x67, acc[3]);
    }
    const float bb = __ldg(b + r);
#pragma unroll
    for (int tp = 0; tp < 4; tp++) {
        float2 v = up2(acc[tp]);
        g_wxb[(size_t)(t0 + 2 * tp) * 2304 + r]     = v.x + bb;
        g_wxb[(size_t)(t0 + 2 * tp + 1) * 2304 + r] = v.y + bb;
    }
}

// ---------------------------------------------------------------- shared memory for scan
struct ScanSmem { float wxb[2048]; __align__(16) float xb[2 * 4 * 768]; };  // 32.7KB

// ---------------------------------------------------------------- kernel 2: the scan (R8 loop, WXB evicted)
// 144 CTAs x 256 threads. CTA: layer l=bid/48, rows [(bid%48)*16,+16).
// Warp w owns rows 2w,2w+1; lane owns cols {4*lane+128*kk+q : kk<6}.
__global__ void __launch_bounds__(256, 1) k_scan(
    const float* __restrict__ x_seq, const float* __restrict__ W,
    const float* __restrict__ lam,
    const float* __restrict__ eta0, const float* __restrict__ eta1p,
    const float* __restrict__ eta2, const float* __restrict__ P_init)
{
    __shared__ ScanSmem sm;
    const int tid = threadIdx.x;
    const int bid = blockIdx.x;
    const int l  = bid / 48;
    const int rb = (bid % 48) * 16;
    const int w = tid >> 5, lane = tid & 31;
    const int r0 = 2 * w;
    const int gr0 = rb + r0, gr1 = gr0 + 1;
    const float* Wl = W + (size_t)l * 589824;
    const int cb = 4 * lane;

    // ---- prefetch wxb slice: sm.wxb[t*16+rl] = g_wxb[t][l*768+rb+rl]
    {
        const int base = l * 768 + rb;
#pragma unroll
        for (int i = 0; i < 8; i++) {
            int idx = tid + 256 * i;          // 0..2047
            int t = idx >> 4, rl = idx & 15;
            sm.wxb[idx] = __ldg(g_wxb + (size_t)t * 2304 + base + rl);
        }
    }

    // ---- persistent state (unified A/M): A: q=P, e=eta, escal=1 | M: q=W.P, e=W, escal=eta1
    u64 q0[12], q1[12], e0[12], e1[12];
    const float* Pl = P_init + (size_t)l * 589824;
#pragma unroll
    for (int kk = 0; kk < 6; kk++) {
        ldg2(q0[2 * kk], q0[2 * kk + 1], Pl + (size_t)gr0 * 768 + cb + 128 * kk);
        ldg2(q1[2 * kk], q1[2 * kk + 1], Pl + (size_t)gr1 * 768 + cb + 128 * kk);
    }
    const float* ep = (l == 0) ? eta0 : ((l == 2) ? eta2 : Wl);
#pragma unroll
    for (int kk = 0; kk < 6; kk++) {
        ldg2(e0[2 * kk], e0[2 * kk + 1], ep + (size_t)gr0 * 768 + cb + 128 * kk);
        ldg2(e1[2 * kk], e1[2 * kk + 1], ep + (size_t)gr1 * 768 + cb + 128 * kk);
    }
    if (l == 1) {
#pragma unroll
        for (int k = 0; k < 12; k++) { q0[k] = mul2(q0[k], e0[k]); q1[k] = mul2(q1[k], e1[k]); }
    }
    const float decay = 1.0f / (1.0f + __expf(-lam[l]));
    const float escal = (l == 1) ? eta1p[0] : 1.0f;
    const float d2v = decay * decay;
    const float a0c = decay * escal;          // coef for h0 in update
    const u64 d2p = pk2(d2v, d2v);
    const int gc0 = l * 768 + rb + r0;
    const unsigned xbs = smem_u32(sm.xb);

    // ---- preload chunk 0 (4 steps = 3072 floats)
#pragma unroll
    for (int i = 0; i < 3; i++)
        cp_async16(xbs + 16 * (tid + 256 * i), x_seq + 4 * (tid + 256 * i));
    cp_commit(); cp_wait<0>();
    __syncthreads();

    // ---- the scan: 32 chunks x (2 batches of 2 steps)
    for (int c = 0; c < 32; c++) {
        if (c < 31) {
            const float* src = x_seq + (size_t)(c + 1) * 3072;
            unsigned dst = xbs + ((c + 1) & 1) * 12288;
#pragma unroll
            for (int i = 0; i < 3; i++)
                cp_async16(dst + 16 * (tid + 256 * i), src + 4 * (tid + 256 * i));
            cp_commit();
        }
        const unsigned xcs = xbs + (c & 1) * 12288;
#pragma unroll
        for (int half = 0; half < 2; half++) {
            const int t = c * 4 + half * 2;
            const unsigned xa0 = xcs + (half * 2) * 3072 + 16 * lane;
            u64 x0[12], x1[12];
#pragma unroll
            for (int kk = 0; kk < 6; kk++) {
                lds2(x0[2 * kk], x0[2 * kk + 1], xa0 + 512 * kk);
                lds2(x1[2 * kk], x1[2 * kk + 1], xa0 + 3072 + 512 * kk);
            }
            // 6 independent dots (all h-independent): u0,u1 per row + v per row
            u64 au00 = 0, au10 = 0, au01 = 0, au11 = 0, av0 = 0, av1 = 0;
#pragma unroll
            for (int k = 0; k < 12; k++) {
                u64 wk = mul2(x0[k], x1[k]);
                au00 = fma2(q0[k], x0[k], au00);
                au10 = fma2(q0[k], x1[k], au10);
                au01 = fma2(q1[k], x0[k], au01);
                au11 = fma2(q1[k], x1[k], au11);
                av0  = fma2(e0[k], wk, av0);
                av1  = fma2(e1[k], wk, av1);
            }
            // packed reductions: A=(u0,u1) row0; B=(u0,u1) row1; C=(v0,v1)
            u64 A = wredsum2(pk2(hsum(au00), hsum(au10)));
            u64 B = wredsum2(pk2(hsum(au01), hsum(au11)));
            u64 C = wredsum2(pk2(hsum(av0),  hsum(av1)));
            float2 fa = up2(A), fb = up2(B), fc = up2(C);
            const float2 wx0 = *(const float2*)(sm.wxb + t * 16 + r0);
            const float2 wx1 = *(const float2*)(sm.wxb + (t + 1) * 16 + r0);
            // h0 = sig(u0 + wxb); h1 = sig(decay*u1 + escal*h0*v + wxb')
            float h00 = sig_fast(fa.x + wx0.x);
            float h01 = sig_fast(fb.x + wx0.y);
            float h10 = sig_fast(fmaf(decay, fa.y, fmaf(escal * h00, fc.x, wx1.x)));
            float h11 = sig_fast(fmaf(decay, fb.y, fmaf(escal * h01, fc.y, wx1.y)));
            if (lane == 0) {
                float2 hv0; hv0.x = h00; hv0.y = h01;
                float2 hv1; hv1.x = h10; hv1.y = h11;
                *(float2*)(g_H + (size_t)t * 2304 + gc0) = hv0;
                *(float2*)(g_H + (size_t)(t + 1) * 2304 + gc0) = hv1;
            }
            // batched update: q = d2*q + e .* (a0*x0 + a1*x1)
            const u64 p00 = pk2(a0c * h00, a0c * h00);
            const u64 p10 = pk2(escal * h10, escal * h10);
            const u64 p01 = pk2(a0c * h01, a0c * h01);
            const u64 p11 = pk2(escal * h11, escal * h11);
#pragma unroll
            for (int k = 0; k < 12; k++) {
                u64 z0 = fma2(p10, x1[k], mul2(p00, x0[k]));
                q0[k] = fma2(e0[k], z0, mul2(q0[k], d2p));
                u64 z1 = fma2(p11, x1[k], mul2(p01, x0[k]));
                q1[k] = fma2(e1[k], z1, mul2(q1[k], d2p));
            }
        }
        if (c < 31) cp_wait<0>();
        __syncthreads();
    }
}

// ---------------------------------------------------------------- kernel 3: readout GEMM (split-K 12)
__global__ void __launch_bounds__(256) k_gemm() {
    __shared__ __align__(16) float Hs[192 * 36];  // [192 j][32 t + pad 4]
    const int ob = blockIdx.x, tb = blockIdx.y, kb = blockIdx.z;
    const int tid = threadIdx.x;
    const int t0 = tb * 32;
#pragma unroll
    for (int i = 0; i < 24; i++) {
        int idx = tid + 256 * i;
        int tl = idx / 192, jl = idx - tl * 192;
        Hs[jl * 36 + tl] = g_H[(size_t)(t0 + tl) * 2304 + kb * 192 + jl];
    }
    __syncthreads();

    u64 acc[16];
#pragma unroll
    for (int i = 0; i < 16; i++) acc[i] = 0;

    const int o = ob * 256 + tid;
    const float* wp = g_wfT + (size_t)(kb * 192) * 768 + o;
    const unsigned hs = smem_u32(Hs);
#pragma unroll 8
    for (int j = 0; j < 192; j++) {
        float wv = __ldg(wp + (size_t)j * 768);
        u64 w2 = pk2(wv, wv);
        const unsigned ha = hs + j * 144;
#pragma unroll
        for (int u = 0; u < 8; u++) {
            u64 h0, h1; lds2(h0, h1, ha + 16 * u);
            acc[2 * u]     = fma2(w2, h0, acc[2 * u]);
            acc[2 * u + 1] = fma2(w2, h1, acc[2 * u + 1]);
        }
    }
    float* pp = g_part + (size_t)kb * 98304 + (size_t)t0 * 768 + o;
#pragma unroll
    for (int u = 0; u < 8; u++) {
        float2 v0 = up2(acc[2 * u]), v1 = up2(acc[2 * u + 1]);
        pp[(size_t)(4 * u + 0) * 768] = v0.x;
        pp[(size_t)(4 * u + 1) * 768] = v0.y;
        pp[(size_t)(4 * u + 2) * 768] = v1.x;
        pp[(size_t)(4 * u + 3) * 768] = v1.y;
    }
}

// ---------------------------------------------------------------- kernel 4: reduce + bias + sigmoid
__global__ void __launch_bounds__(256) k_reduce(const float* __restrict__ bf,
                                                float* __restrict__ y) {
    const int i = blockIdx.x * 256 + threadIdx.x;  // 0..98303
    int o = i % 768;
    float v[12];
#pragma unroll
    for (int k = 0; k < 12; k++) v[k] = __ldg(g_part + (size_t)k * 98304 + i);
    float s01 = v[0] + v[1], s23 = v[2] + v[3], s45 = v[4] + v[5];
    float s67 = v[6] + v[7], s89 = v[8] + v[9], sab = v[10] + v[11];
    float s = ((s01 + s23) + (s45 + s67)) + ((s89 + sab) + __ldg(bf + o));
    y[i] = sig_fast(s);
}

// ---------------------------------------------------------------- launch
extern "C" void kernel_launch(void* const* d_in, const int* in_sizes, int n_in,
                              void* d_out, int out_size) {
    const float* x    = (const float*)d_in[0];  // (128, 768)
    const float* W    = (const float*)d_in[1];  // (3, 768, 768)
    const float* b    = (const float*)d_in[2];  // (3, 768)
    const float* lam  = (const float*)d_in[3];  // (3,)
    const float* eta0 = (const float*)d_in[4];  // (768, 768)
    const float* eta1 = (const float*)d_in[5];  // scalar
    const float* eta2 = (const float*)d_in[6];  // (768, 768)
    const float* wf   = (const float*)d_in[7];  // (768, 2304)
    const float* bf   = (const float*)d_in[8];  // (768,)
    const float* P0   = (const float*)d_in[9];  // (3, 768, 768)
    float* y = (float*)d_out;                   // (128, 768)

    k_pre<<<864, 256>>>(wf, W);
    k_wxb<<<dim3(9, 16), 256>>>(x, b);
    k_scan<<<144, 256>>>(x, W, lam, eta0, eta1, eta2, P0);
    k_gemm<<<dim3(3, 4, 12), 256>>>();
    k_reduce<<<384, 256>>>(bf, y);
}

// round 13
// speedup vs baseline: 1.5195x; 1.4033x over previous
#include <cuda_runtime.h>
#include <cstddef>

#define FULLMASK 0xffffffffu
typedef unsigned long long u64;

// T=128, D=768, HID=768, L=3, OUT=768, LH=2304
__device__ float g_H[128 * 2304];        // h_cat per step
__device__ float g_wfT[2304 * 768];      // transposed w_final
__device__ float g_part[12 * 128 * 768]; // split-K partials

// ---------------------------------------------------------------- helpers
__device__ __forceinline__ unsigned smem_u32(const void* p) {
    unsigned a;
    asm("{ .reg .u64 t; cvta.to.shared.u64 t, %1; cvt.u32.u64 %0, t; }"
        : "=r"(a) : "l"(p));
    return a;
}
__device__ __forceinline__ void cp_async16(unsigned d, const void* src) {
    asm volatile("cp.async.ca.shared.global [%0], [%1], 16;\n" :: "r"(d), "l"(src));
}
__device__ __forceinline__ void cp_commit() { asm volatile("cp.async.commit_group;\n" ::); }
template <int N>
__device__ __forceinline__ void cp_wait() { asm volatile("cp.async.wait_group %0;\n" :: "n"(N)); }

__device__ __forceinline__ u64 fma2(u64 a, u64 b, u64 c) {
    u64 d; asm("fma.rn.f32x2 %0, %1, %2, %3;" : "=l"(d) : "l"(a), "l"(b), "l"(c)); return d;
}
__device__ __forceinline__ u64 mul2(u64 a, u64 b) {
    u64 d; asm("mul.rn.f32x2 %0, %1, %2;" : "=l"(d) : "l"(a), "l"(b)); return d;
}
__device__ __forceinline__ u64 add2(u64 a, u64 b) {
    u64 d; asm("add.rn.f32x2 %0, %1, %2;" : "=l"(d) : "l"(a), "l"(b)); return d;
}
__device__ __forceinline__ u64 pk2(float x, float y) {
    u64 d; asm("mov.b64 %0, {%1, %2};" : "=l"(d) : "f"(x), "f"(y)); return d;
}
__device__ __forceinline__ float2 up2(u64 v) {
    float2 r; asm("mov.b64 {%0, %1}, %2;" : "=f"(r.x), "=f"(r.y) : "l"(v)); return r;
}
__device__ __forceinline__ void lds2(u64& a, u64& b, unsigned addr) {
    asm volatile("ld.shared.v2.b64 {%0, %1}, [%2];" : "=l"(a), "=l"(b) : "r"(addr));
}
__device__ __forceinline__ void ldg2(u64& a, u64& b, const float* p) {
    asm volatile("ld.global.nc.v2.b64 {%0, %1}, [%2];" : "=l"(a), "=l"(b) : "l"(p));
}
__device__ __forceinline__ float sig_fast(float z) {
    float e = __expf(-z);
    return __fdividef(1.0f, 1.0f + e);
}
__device__ __forceinline__ float hsum(u64 v) { float2 f = up2(v); return f.x + f.y; }
// HW cross-lane sum via REDUX.SUM (s32, sm_80+ => legal in compute_100 PTX).
// Fixed-point bridge: scale 2^18, range +-8192 >> partial magnitudes O(10^2).
__device__ __forceinline__ float redux_f(float v) {
    const float S = 262144.0f, IS = 3.814697265625e-06f;  // 2^18, 2^-18
    int i = __float2int_rn(v * S);
    int s = __reduce_add_sync(FULLMASK, i);
    return (float)s * IS;
}

// ---------------------------------------------------------------- shared memory
struct ScanSmem { float wxb[2048]; __align__(16) float xb[2 * 4 * 768]; };  // 32.7KB
union Smem {
    ScanSmem s;
    float tile[64 * 65];          // transpose prologue
};

// ---------------------------------------------------------------- kernel 1: transpose prologue + scan
// 144 CTAs x 256 threads. CTA j: layer l=j/48, rows [(j%48)*16,+16).
// Warp w owns rows 2w,2w+1; lane owns cols {4*lane+128*kk+q : kk<6}.
__global__ void __launch_bounds__(256, 1) k_scan(
    const float* __restrict__ x_seq, const float* __restrict__ W,
    const float* __restrict__ b, const float* __restrict__ lam,
    const float* __restrict__ eta0, const float* __restrict__ eta1p,
    const float* __restrict__ eta2, const float* __restrict__ P_init,
    const float* __restrict__ wf)
{
    __shared__ Smem sm;
    const int tid = threadIdx.x;
    const int bid = blockIdx.x;

    // ---- prologue: wf transpose, 3 tiles of 64x64 per CTA (432 total)
    {
        const int rr = tid >> 4, cc = (tid & 15) * 4;
#pragma unroll 1
        for (int it = 0; it < 3; it++) {
            const int tt = bid * 3 + it;
            const int o0 = (tt % 12) * 64;
            const int j0 = (tt / 12) * 64;
#pragma unroll
            for (int i = 0; i < 4; i++) {
                int r = rr + 16 * i;
                float4 v = *(const float4*)(wf + (size_t)(o0 + r) * 2304 + j0 + cc);
                sm.tile[r * 65 + cc + 0] = v.x; sm.tile[r * 65 + cc + 1] = v.y;
                sm.tile[r * 65 + cc + 2] = v.z; sm.tile[r * 65 + cc + 3] = v.w;
            }
            __syncthreads();
#pragma unroll
            for (int i = 0; i < 4; i++) {
                int jj = rr + 16 * i;
                float4 v;
                v.x = sm.tile[(cc + 0) * 65 + jj];
                v.y = sm.tile[(cc + 1) * 65 + jj];
                v.z = sm.tile[(cc + 2) * 65 + jj];
                v.w = sm.tile[(cc + 3) * 65 + jj];
                *(float4*)(g_wfT + (size_t)(j0 + jj) * 768 + o0 + cc) = v;
            }
            __syncthreads();
        }
    }

    // ---- scan setup
    const int l  = bid / 48;
    const int rb = (bid % 48) * 16;
    const int w = tid >> 5, lane = tid & 31;
    const int r0 = 2 * w;
    const int gr0 = rb + r0, gr1 = gr0 + 1;
    const float* Wl = W + (size_t)l * 589824;
    const int cb = 4 * lane;
    float* wxb = sm.s.wxb;

    // ---- WXB precompute: wxb[t][r] = W[r,:]@x_t + b[r]
    {
        u64 wv0[12], wv1[12];
#pragma unroll
        for (int kk = 0; kk < 6; kk++) {
            ldg2(wv0[2 * kk], wv0[2 * kk + 1], Wl + (size_t)gr0 * 768 + cb + 128 * kk);
            ldg2(wv1[2 * kk], wv1[2 * kk + 1], Wl + (size_t)gr1 * 768 + cb + 128 * kk);
        }
        const float bb0 = b[l * 768 + gr0], bb1 = b[l * 768 + gr1];

        float4* xf4 = (float4*)sm.s.xb;
        const float4* xs4 = (const float4*)x_seq;
        const unsigned xfs = smem_u32(sm.s.xb);
        for (int c0 = 0; c0 < 128; c0 += 8) {
#pragma unroll
            for (int i = 0; i < 6; i++)
                xf4[tid + 256 * i] = xs4[(size_t)c0 * 192 + tid + 256 * i];
            __syncthreads();
#pragma unroll
            for (int tt = 0; tt < 8; tt++) {
                const unsigned xa = xfs + tt * 3072 + 16 * lane;
                u64 a0 = 0, a1 = 0, a2 = 0, a3 = 0;
#pragma unroll
                for (int kk = 0; kk < 6; kk++) {
                    u64 x0, x1; lds2(x0, x1, xa + 512 * kk);
                    a0 = fma2(wv0[2 * kk], x0, a0); a2 = fma2(wv0[2 * kk + 1], x1, a2);
                    a1 = fma2(wv1[2 * kk], x0, a1); a3 = fma2(wv1[2 * kk + 1], x1, a3);
                }
                float s0 = redux_f(hsum(add2(a0, a2)));
                float s1 = redux_f(hsum(add2(a1, a3)));
                if (lane == 0) {
                    wxb[(c0 + tt) * 16 + r0]     = s0 + bb0;
                    wxb[(c0 + tt) * 16 + r0 + 1] = s1 + bb1;
                }
            }
            __syncthreads();
        }
    }

    // ---- persistent state (unified A/M): A: q=P, e=eta, escal=1 | M: q=W.P, e=W, escal=eta1
    u64 q0[12], q1[12], e0[12], e1[12];
    const float* Pl = P_init + (size_t)l * 589824;
#pragma unroll
    for (int kk = 0; kk < 6; kk++) {
        ldg2(q0[2 * kk], q0[2 * kk + 1], Pl + (size_t)gr0 * 768 + cb + 128 * kk);
        ldg2(q1[2 * kk], q1[2 * kk + 1], Pl + (size_t)gr1 * 768 + cb + 128 * kk);
    }
    const float* ep = (l == 0) ? eta0 : ((l == 2) ? eta2 : Wl);
#pragma unroll
    for (int kk = 0; kk < 6; kk++) {
        ldg2(e0[2 * kk], e0[2 * kk + 1], ep + (size_t)gr0 * 768 + cb + 128 * kk);
        ldg2(e1[2 * kk], e1[2 * kk + 1], ep + (size_t)gr1 * 768 + cb + 128 * kk);
    }
    if (l == 1) {
#pragma unroll
        for (int k = 0; k < 12; k++) { q0[k] = mul2(q0[k], e0[k]); q1[k] = mul2(q1[k], e1[k]); }
    }
    const float decay = 1.0f / (1.0f + __expf(-lam[l]));
    const float escal = (l == 1) ? eta1p[0] : 1.0f;
    const float d2v = decay * decay;
    const float a0c = decay * escal;          // coef for h0 in update
    const u64 d2p = pk2(d2v, d2v);
    const int gc0 = l * 768 + rb + r0;
    const unsigned xbs = smem_u32(sm.s.xb);

    // ---- preload chunk 0 (4 steps = 3072 floats)
#pragma unroll
    for (int i = 0; i < 3; i++)
        cp_async16(xbs + 16 * (tid + 256 * i), x_seq + 4 * (tid + 256 * i));
    cp_commit(); cp_wait<0>();
    __syncthreads();

    // ---- the scan: 32 chunks x (2 batches of 2 steps)
    for (int c = 0; c < 32; c++) {
        if (c < 31) {
            const float* src = x_seq + (size_t)(c + 1) * 3072;
            unsigned dst = xbs + ((c + 1) & 1) * 12288;
#pragma unroll
            for (int i = 0; i < 3; i++)
                cp_async16(dst + 16 * (tid + 256 * i), src + 4 * (tid + 256 * i));
            cp_commit();
        }
        const unsigned xcs = xbs + (c & 1) * 12288;
#pragma unroll
        for (int half = 0; half < 2; half++) {
            const int t = c * 4 + half * 2;
            const unsigned xa0 = xcs + (half * 2) * 3072 + 16 * lane;
            u64 x0[12], x1[12];
#pragma unroll
            for (int kk = 0; kk < 6; kk++) {
                lds2(x0[2 * kk], x0[2 * kk + 1], xa0 + 512 * kk);
                lds2(x1[2 * kk], x1[2 * kk + 1], xa0 + 3072 + 512 * kk);
            }
            // 6 independent dots (all h-independent): u0,u1 per row + v per row
            u64 au00 = 0, au10 = 0, au01 = 0, au11 = 0, av0 = 0, av1 = 0;
#pragma unroll
            for (int k = 0; k < 12; k++) {
                u64 wk = mul2(x0[k], x1[k]);
                au00 = fma2(q0[k], x0[k], au00);
                au10 = fma2(q0[k], x1[k], au10);
                au01 = fma2(q1[k], x0[k], au01);
                au11 = fma2(q1[k], x1[k], au11);
                av0  = fma2(e0[k], wk, av0);
                av1  = fma2(e1[k], wk, av1);
            }
            // HW reductions (all 6 independent; REDUX.SUM broadcasts to all lanes)
            float ru00 = redux_f(hsum(au00));
            float ru10 = redux_f(hsum(au10));
            float ru01 = redux_f(hsum(au01));
            float ru11 = redux_f(hsum(au11));
            float rv0  = redux_f(hsum(av0));
            float rv1  = redux_f(hsum(av1));
            const float2 wx0 = *(const float2*)(sm.s.wxb + t * 16 + r0);
            const float2 wx1 = *(const float2*)(sm.s.wxb + (t + 1) * 16 + r0);
            // h0 = sig(u0 + wxb); h1 = sig(decay*u1 + escal*h0*v + wxb')
            float h00 = sig_fast(ru00 + wx0.x);
            float h01 = sig_fast(ru01 + wx0.y);
            float h10 = sig_fast(fmaf(decay, ru10, fmaf(escal * h00, rv0, wx1.x)));
            float h11 = sig_fast(fmaf(decay, ru11, fmaf(escal * h01, rv1, wx1.y)));
            if (lane == 0) {
                float2 hv0; hv0.x = h00; hv0.y = h01;
                float2 hv1; hv1.x = h10; hv1.y = h11;
                *(float2*)(g_H + (size_t)t * 2304 + gc0) = hv0;
                *(float2*)(g_H + (size_t)(t + 1) * 2304 + gc0) = hv1;
            }
            // batched update: q = d2*q + e .* (a0*x0 + a1*x1)
            const u64 p00 = pk2(a0c * h00, a0c * h00);
            const u64 p10 = pk2(escal * h10, escal * h10);
            const u64 p01 = pk2(a0c * h01, a0c * h01);
            const u64 p11 = pk2(escal * h11, escal * h11);
#pragma unroll
            for (int k = 0; k < 12; k++) {
                u64 z0 = fma2(p10, x1[k], mul2(p00, x0[k]));
                q0[k] = fma2(e0[k], z0, mul2(q0[k], d2p));
                u64 z1 = fma2(p11, x1[k], mul2(p01, x0[k]));
                q1[k] = fma2(e1[k], z1, mul2(q1[k], d2p));
            }
        }
        if (c < 31) cp_wait<0>();
        __syncthreads();
    }
}

// ---------------------------------------------------------------- kernel 2: readout GEMM (split-K 12)
__global__ void __launch_bounds__(256) k_gemm() {
    __shared__ __align__(16) float Hs[192 * 36];  // [192 j][32 t + pad 4]
    const int ob = blockIdx.x, tb = blockIdx.y, kb = blockIdx.z;
    const int tid = threadIdx.x;
    const int t0 = tb * 32;
#pragma unroll
    for (int i = 0; i < 24; i++) {
        int idx = tid + 256 * i;
        int tl = idx / 192, jl = idx - tl * 192;
        Hs[jl * 36 + tl] = g_H[(size_t)(t0 + tl) * 2304 + kb * 192 + jl];
    }
    __syncthreads();

    u64 acc[16];
#pragma unroll
    for (int i = 0; i < 16; i++) acc[i] = 0;

    const int o = ob * 256 + tid;
    const float* wp = g_wfT + (size_t)(kb * 192) * 768 + o;
    const unsigned hs = smem_u32(Hs);
#pragma unroll 8
    for (int j = 0; j < 192; j++) {
        float wv = __ldg(wp + (size_t)j * 768);
        u64 w2 = pk2(wv, wv);
        const unsigned ha = hs + j * 144;
#pragma unroll
        for (int u = 0; u < 8; u++) {
            u64 h0, h1; lds2(h0, h1, ha + 16 * u);
            acc[2 * u]     = fma2(w2, h0, acc[2 * u]);
            acc[2 * u + 1] = fma2(w2, h1, acc[2 * u + 1]);
        }
    }
    float* pp = g_part + (size_t)kb * 98304 + (size_t)t0 * 768 + o;
#pragma unroll
    for (int u = 0; u < 8; u++) {
        float2 v0 = up2(acc[2 * u]), v1 = up2(acc[2 * u + 1]);
        pp[(size_t)(4 * u + 0) * 768] = v0.x;
        pp[(size_t)(4 * u + 1) * 768] = v0.y;
        pp[(size_t)(4 * u + 2) * 768] = v1.x;
        pp[(size_t)(4 * u + 3) * 768] = v1.y;
    }
}

// ---------------------------------------------------------------- kernel 3: reduce + bias + sigmoid
// 384 blocks x 256 threads, 1 scalar/thread, 12 independent LDGs (MLP 12)
__global__ void __launch_bounds__(256) k_reduce(const float* __restrict__ bf,
                                                float* __restrict__ y) {
    const int i = blockIdx.x * 256 + threadIdx.x;  // 0..98303
    int o = i % 768;
    float v[12];
#pragma unroll
    for (int k = 0; k < 12; k++) v[k] = __ldg(g_part + (size_t)k * 98304 + i);
    float s01 = v[0] + v[1], s23 = v[2] + v[3], s45 = v[4] + v[5];
    float s67 = v[6] + v[7], s89 = v[8] + v[9], sab = v[10] + v[11];
    float s = ((s01 + s23) + (s45 + s67)) + ((s89 + sab) + __ldg(bf + o));
    y[i] = sig_fast(s);
}

// ---------------------------------------------------------------- launch
extern "C" void kernel_launch(void* const* d_in, const int* in_sizes, int n_in,
                              void* d_out, int out_size) {
    const float* x    = (const float*)d_in[0];  // (128, 768)
    const float* W    = (const float*)d_in[1];  // (3, 768, 768)
    const float* b    = (const float*)d_in[2];  // (3, 768)
    const float* lam  = (const float*)d_in[3];  // (3,)
    const float* eta0 = (const float*)d_in[4];  // (768, 768)
    const float* eta1 = (const float*)d_in[5];  // scalar
    const float* eta2 = (const float*)d_in[6];  // (768, 768)
    const float* wf   = (const float*)d_in[7];  // (768, 2304)
    const float* bf   = (const float*)d_in[8];  // (768,)
    const float* P0   = (const float*)d_in[9];  // (3, 768, 768)
    float* y = (float*)d_out;                   // (128, 768)

    k_scan<<<144, 256>>>(x, W, b, lam, eta0, eta1, eta2, P0, wf);
    k_gemm<<<dim3(3, 4, 12), 256>>>();
    k_reduce<<<384, 256>>>(bf, y);
}